// round 2
// baseline (speedup 1.0000x reference)
#include <cuda_runtime.h>
#include <math.h>

#define Bb   2
#define Tt   512
#define Hh   16
#define BHT  16384

typedef unsigned long long u64;

// ---------------- scratch ----------------------------------------------------
__device__ float g_q [BHT*64];
__device__ float g_k [BHT*64];
__device__ float g_v [BHT*64];
__device__ float g_km[BHT*32];
__device__ float g_k2[BHT];
__device__ float g_U [BHT*128];
__device__ float g_m [BHT*32];
__device__ float g_c [BHT];
__device__ float g_pacc[2][BHT*64];
__device__ float g_psum[2][BHT];
__device__ float g_ao[Bb*Tt*1024];

// ---------------- f32x2 helpers ----------------------------------------------
__device__ __forceinline__ u64 pk2(float a, float b) {
    u64 r; asm("mov.b64 %0,{%1,%2};" : "=l"(r) : "f"(a), "f"(b)); return r;
}
__device__ __forceinline__ void fma2(u64 &d, u64 a, u64 b) {
    asm("fma.rn.f32x2 %0,%1,%2,%0;" : "+l"(d) : "l"(a), "l"(b));
}
__device__ __forceinline__ float2 up2(u64 a) {
    float2 r; asm("mov.b64 {%0,%1},%2;" : "=f"(r.x), "=f"(r.y) : "l"(a)); return r;
}

// ---------------- GEMM: 128x64 tile, BK=16, double-buffered, f32x2 ----------
// mode 0: A = x, W by blockIdx.z (Wq/Wk/Wv); RoPE fused for z<2; head-split store
// mode 1: A = g_ao, W = W0 (Wo); plain store to Cout
__global__ void __launch_bounds__(256, 2) gemm2(
    const float* __restrict__ A,
    const float* __restrict__ W0, const float* __restrict__ W1,
    const float* __restrict__ W2,
    float* __restrict__ Cout, int mode)
{
    __shared__ float sA[2][16][132];
    __shared__ float sB[2][16][64];

    const float* Ap = (mode == 0) ? A : g_ao;
    const float* Wm = (mode == 0)
        ? (blockIdx.z == 0 ? W0 : (blockIdx.z == 1 ? W1 : W2))
        : W0;

    int tid = threadIdx.x;
    int tx = tid & 15, ty = tid >> 4;
    int row0 = blockIdx.y * 128, col0 = blockIdx.x * 64;

    int ar = tid >> 1, ak = (tid & 1) * 8;   // A: 128 rows x 16 k
    int br = tid >> 4, bc = (tid & 15) * 4;  // B: 16 rows  x 64 cols

    u64 acc[4][4];
    #pragma unroll
    for (int i = 0; i < 4; i++)
        #pragma unroll
        for (int j = 0; j < 4; j++) acc[i][j] = 0ull;

    const float* Arow = Ap + (row0 + ar) * 1024 + ak;
    const float* Brow = Wm + br * 1024 + col0 + bc;

    float4 pa0 = *(const float4*)(Arow);
    float4 pa1 = *(const float4*)(Arow + 4);
    float4 pb  = *(const float4*)(Brow);

    // store tile 0 into buf 0 (A transposed)
    {
        float* sa = &sA[0][0][0];
        sa[(ak+0)*132+ar] = pa0.x; sa[(ak+1)*132+ar] = pa0.y;
        sa[(ak+2)*132+ar] = pa0.z; sa[(ak+3)*132+ar] = pa0.w;
        sa[(ak+4)*132+ar] = pa1.x; sa[(ak+5)*132+ar] = pa1.y;
        sa[(ak+6)*132+ar] = pa1.z; sa[(ak+7)*132+ar] = pa1.w;
        *(float4*)&sB[0][br][bc] = pb;
    }
    __syncthreads();

    int cur = 0;
    for (int t = 0; t < 64; t++) {
        if (t < 63) {
            pa0 = *(const float4*)(Arow + (t + 1) * 16);
            pa1 = *(const float4*)(Arow + (t + 1) * 16 + 4);
            pb  = *(const float4*)(Brow + (t + 1) * 16384);
        }
        #pragma unroll
        for (int k = 0; k < 16; k++) {
            const float* sa = &sA[cur][k][ty * 8];
            longlong2 a01 = *(const longlong2*)(sa);
            longlong2 a23 = *(const longlong2*)(sa + 4);
            float4 bv = *(const float4*)&sB[cur][k][tx * 4];
            u64 b0 = pk2(bv.x, bv.x), b1 = pk2(bv.y, bv.y);
            u64 b2 = pk2(bv.z, bv.z), b3 = pk2(bv.w, bv.w);
            u64 ap0 = (u64)a01.x, ap1 = (u64)a01.y;
            u64 ap2 = (u64)a23.x, ap3 = (u64)a23.y;
            fma2(acc[0][0], ap0, b0); fma2(acc[0][1], ap0, b1);
            fma2(acc[0][2], ap0, b2); fma2(acc[0][3], ap0, b3);
            fma2(acc[1][0], ap1, b0); fma2(acc[1][1], ap1, b1);
            fma2(acc[1][2], ap1, b2); fma2(acc[1][3], ap1, b3);
            fma2(acc[2][0], ap2, b0); fma2(acc[2][1], ap2, b1);
            fma2(acc[2][2], ap2, b2); fma2(acc[2][3], ap2, b3);
            fma2(acc[3][0], ap3, b0); fma2(acc[3][1], ap3, b1);
            fma2(acc[3][2], ap3, b2); fma2(acc[3][3], ap3, b3);
        }
        if (t < 63) {
            int nb = cur ^ 1;
            float* sa = &sA[nb][0][0];
            sa[(ak+0)*132+ar] = pa0.x; sa[(ak+1)*132+ar] = pa0.y;
            sa[(ak+2)*132+ar] = pa0.z; sa[(ak+3)*132+ar] = pa0.w;
            sa[(ak+4)*132+ar] = pa1.x; sa[(ak+5)*132+ar] = pa1.y;
            sa[(ak+6)*132+ar] = pa1.z; sa[(ak+7)*132+ar] = pa1.w;
            *(float4*)&sB[nb][br][bc] = pb;
        }
        __syncthreads();
        cur ^= 1;
    }

    // unpack accumulators
    float out[8][4];
    #pragma unroll
    for (int ip = 0; ip < 4; ip++)
        #pragma unroll
        for (int j = 0; j < 4; j++) {
            float2 f = up2(acc[ip][j]);
            out[2*ip][j] = f.x; out[2*ip+1][j] = f.y;
        }

    if (mode == 1) {
        #pragma unroll
        for (int r = 0; r < 8; r++) {
            int row = row0 + ty * 8 + r;
            float4 o = make_float4(out[r][0], out[r][1], out[r][2], out[r][3]);
            *(float4*)&Cout[row * 1024 + col0 + tx * 4] = o;
        }
        return;
    }

    int z = blockIdx.z;
    float* dst = (z == 0) ? g_q : (z == 1) ? g_k : g_v;
    int h = col0 >> 6;
    int dh0 = tx * 4;

    if (z == 2) {
        #pragma unroll
        for (int r = 0; r < 8; r++) {
            int row = row0 + ty * 8 + r;
            int b = row >> 9, tpos = row & 511;
            float4 o = make_float4(out[r][0], out[r][1], out[r][2], out[r][3]);
            *(float4*)&dst[(((b << 4) + h) * 512 + tpos) * 64 + dh0] = o;
        }
    } else {
        // fused RoPE: partner column dh^32 lives on thread tx^8 (lane^8)
        float invf[4];
        #pragma unroll
        for (int c = 0; c < 4; c++) {
            int dsub = (tx * 4 + c) & 31;
            invf[c] = expf(-((float)(2 * dsub) / 64.0f) * 9.210340371976184f);
        }
        bool hiHalf = (tx & 8) != 0;
        #pragma unroll
        for (int r = 0; r < 8; r++) {
            int row = row0 + ty * 8 + r;
            int b = row >> 9, tpos = row & 511;
            float4 o;
            #pragma unroll
            for (int c = 0; c < 4; c++) {
                float v  = out[r][c];
                float pv = __shfl_xor_sync(0xffffffffu, v, 8);
                float s, cs;
                sincosf((float)tpos * invf[c], &s, &cs);
                float rr = hiHalf ? (pv * s + v * cs) : (v * cs - pv * s);
                (&o.x)[c] = rr;
            }
            *(float4*)&dst[(((b << 4) + h) * 512 + tpos) * 64 + dh0] = o;
        }
    }
}

// ---------------- metric: km, k2, U, m = qm + w, c = q2 + |Uq|^2 -------------
__global__ void __launch_bounds__(256) metric_kernel(
    const float* __restrict__ Wqm, const float* __restrict__ Wkm,
    const float* __restrict__ Wmetric)
{
    __shared__ float sWqm[64 * 32];
    __shared__ float sWkm[64 * 32];
    __shared__ float sWm [32 * 128];
    int tid = threadIdx.x;
    for (int i = tid; i < 64 * 32; i += 256) { sWqm[i] = Wqm[i]; sWkm[i] = Wkm[i]; }
    for (int i = tid; i < 32 * 128; i += 256) { sWm[i] = Wmetric[i]; }
    __syncthreads();

    const unsigned FULL = 0xffffffffu;
    int w = tid >> 5, lane = tid & 31;
    int tok = blockIdx.x * 8 + w;

    const float* q = g_q + tok * 64;
    const float* k = g_k + tok * 64;
    float a0 = q[lane], a1 = q[lane + 32];
    float b0 = k[lane], b1 = k[lane + 32];

    float accq = 0.f, acck = 0.f;
    #pragma unroll
    for (int d = 0; d < 32; d++) {
        float qd = __shfl_sync(FULL, a0, d);
        float kd = __shfl_sync(FULL, b0, d);
        accq += qd * sWqm[d * 32 + lane];
        acck += kd * sWkm[d * 32 + lane];
    }
    #pragma unroll
    for (int d = 0; d < 32; d++) {
        float qd = __shfl_sync(FULL, a1, d);
        float kd = __shfl_sync(FULL, b1, d);
        accq += qd * sWqm[(d + 32) * 32 + lane];
        acck += kd * sWkm[(d + 32) * 32 + lane];
    }
    float qmv = 1.f / (1.f + expf(-accq));
    float kmv = 1.f / (1.f + expf(-acck));
    g_km[tok * 32 + lane] = kmv;

    float q2 = qmv * qmv, k2 = kmv * kmv;
    #pragma unroll
    for (int o = 16; o > 0; o >>= 1) {
        q2 += __shfl_xor_sync(FULL, q2, o);
        k2 += __shfl_xor_sync(FULL, k2, o);
    }
    if (lane == 0) g_k2[tok] = k2;

    // U[tok, d=lane, r] = sum_dd qm[dd] * Wmetric[dd, lane*4+r]
    float u0 = 0.f, u1 = 0.f, u2 = 0.f, u3 = 0.f;
    #pragma unroll
    for (int d = 0; d < 32; d++) {
        float qd = __shfl_sync(FULL, qmv, d);
        float4 wv = *(const float4*)&sWm[d * 128 + lane * 4];
        u0 += qd * wv.x; u1 += qd * wv.y; u2 += qd * wv.z; u3 += qd * wv.w;
    }
    *(float4*)&g_U[tok * 128 + lane * 4] = make_float4(u0, u1, u2, u3);

    // Uq_r = sum_d U[d][r] * qm[d]
    float p0 = u0 * qmv, p1 = u1 * qmv, p2 = u2 * qmv, p3 = u3 * qmv;
    #pragma unroll
    for (int o = 16; o > 0; o >>= 1) {
        p0 += __shfl_xor_sync(FULL, p0, o);
        p1 += __shfl_xor_sync(FULL, p1, o);
        p2 += __shfl_xor_sync(FULL, p2, o);
        p3 += __shfl_xor_sync(FULL, p3, o);
    }
    // w_d = sum_r Uq_r * U[d][r];  m = qm + w
    float wd = p0 * u0 + p1 * u1 + p2 * u2 + p3 * u3;
    g_m[tok * 32 + lane] = qmv + wd;
    if (lane == 0)
        g_c[tok] = q2 + p0 * p0 + p1 * p1 + p2 * p2 + p3 * p3;
}

// ---------------- attention --------------------------------------------------
// dist(i,j) = c_i + k2_j - 2 m_i.km_j + sum_r (U_i.km_j)^2 ; p = exp(-dist/T)
// block: (p=0..14 -> qt,jc ; bh). 256 thr. Per tile: phaseA scores -> sP,
// phaseB P@V with f32x2. Partials -> g_pacc/g_psum[jc], merged by merge_kernel.
__global__ void __launch_bounds__(256, 2) attn2(const float* __restrict__ temp_ptr)
{
    __shared__ float sKm[64 * 32];
    __shared__ float sV [64 * 64];
    __shared__ float sP [64 * 65];
    __shared__ float sK2[64];
    __shared__ float sC [64];
    __shared__ float sSum[64 * 4];

    int pidx = 14 - blockIdx.x;          // heavy blocks first
    int qt, jc;
    if (pidx == 0) { qt = 0; jc = 0; }
    else { qt = (pidx + 1) >> 1; jc = (pidx + 1) & 1; }
    int bh = blockIdx.y;
    int tok0 = bh * 512 + qt * 64;
    int tid = threadIdx.x;
    int ia = tid >> 2, jq = tid & 3;
    float invT = 1.0f / fmaxf(temp_ptr[0], 0.5f);

    if (tid < 64) sC[tid] = g_c[tok0 + tid];

    const float* Urow = g_U + (tok0 + ia) * 128;
    const float* Mrow = g_m + (tok0 + ia) * 32;
    int iG = qt * 64 + ia;

    u64 vacc[8];
    #pragma unroll
    for (int e = 0; e < 8; e++) vacc[e] = 0ull;
    float runSum = 0.f;

    int ntile = ((qt - jc) >> 1) + 1;
    for (int s = 0; s < ntile; s++) {
        int jt = jc + 2 * s;
        int j0 = jt * 64;
        int tokJ = bh * 512 + j0;
        __syncthreads();
        // stage km (512 f4), V (1024 f4), k2
        #pragma unroll
        for (int e = 0; e < 2; e++) {
            int idx = tid + e * 256;
            *(float4*)&sKm[idx * 4] = *(const float4*)&g_km[tokJ * 32 + idx * 4];
        }
        #pragma unroll
        for (int e = 0; e < 4; e++) {
            int idx = tid + e * 256;
            *(float4*)&sV[idx * 4] = *(const float4*)&g_v[tokJ * 64 + idx * 4];
        }
        if (tid < 64) sK2[tid] = g_k2[tokJ + tid];
        __syncthreads();

        // -------- phase A: scores for 16 j's (4 chunks of 4) --------
        float ci = sC[ia];
        bool diag = (jt == qt);
        #pragma unroll
        for (int c4 = 0; c4 < 4; c4++) {
            int jb = jq * 16 + c4 * 4;
            float qk[4];
            u64 uk0[4], uk1[4];
            #pragma unroll
            for (int j = 0; j < 4; j++) { qk[j] = 0.f; uk0[j] = 0ull; uk1[j] = 0ull; }
            #pragma unroll
            for (int dd = 0; dd < 8; dd++) {
                float4 mv = *(const float4*)&Mrow[dd * 4];
                longlong2 ud0 = *(const longlong2*)&Urow[(dd * 4 + 0) * 4];
                longlong2 ud1 = *(const longlong2*)&Urow[(dd * 4 + 1) * 4];
                longlong2 ud2 = *(const longlong2*)&Urow[(dd * 4 + 2) * 4];
                longlong2 ud3 = *(const longlong2*)&Urow[(dd * 4 + 3) * 4];
                #pragma unroll
                for (int j = 0; j < 4; j++) {
                    float4 kv = *(const float4*)&sKm[(jb + j) * 32 + dd * 4];
                    qk[j] += mv.x * kv.x + mv.y * kv.y + mv.z * kv.z + mv.w * kv.w;
                    u64 kd;
                    kd = pk2(kv.x, kv.x); fma2(uk0[j], (u64)ud0.x, kd); fma2(uk1[j], (u64)ud0.y, kd);
                    kd = pk2(kv.y, kv.y); fma2(uk0[j], (u64)ud1.x, kd); fma2(uk1[j], (u64)ud1.y, kd);
                    kd = pk2(kv.z, kv.z); fma2(uk0[j], (u64)ud2.x, kd); fma2(uk1[j], (u64)ud2.y, kd);
                    kd = pk2(kv.w, kv.w); fma2(uk0[j], (u64)ud3.x, kd); fma2(uk1[j], (u64)ud3.y, kd);
                }
            }
            #pragma unroll
            for (int j = 0; j < 4; j++) {
                float2 ua = up2(uk0[j]);
                float2 ub = up2(uk1[j]);
                float dist = ci + sK2[jb + j] - 2.f * qk[j]
                           + ua.x * ua.x + ua.y * ua.y + ub.x * ub.x + ub.y * ub.y;
                dist = fmaxf(dist, 0.f);
                float p = __expf(-dist * invT);
                if (diag && (jb + j) > ia) p = 0.f;
                sP[ia * 65 + jb + j] = p;
                runSum += p;
            }
        }
        __syncthreads();

        // -------- phase B: vacc += P @ V (16 cols per thread, paired) --------
        const float* Vcol = sV + jq * 16;
        #pragma unroll 2
        for (int j = 0; j < 64; j++) {
            float pv = sP[ia * 65 + j];
            u64 pp = pk2(pv, pv);
            longlong2 v0 = *(const longlong2*)(Vcol + j * 64);
            longlong2 v1 = *(const longlong2*)(Vcol + j * 64 + 4);
            longlong2 v2 = *(const longlong2*)(Vcol + j * 64 + 8);
            longlong2 v3 = *(const longlong2*)(Vcol + j * 64 + 12);
            fma2(vacc[0], pp, (u64)v0.x); fma2(vacc[1], pp, (u64)v0.y);
            fma2(vacc[2], pp, (u64)v1.x); fma2(vacc[3], pp, (u64)v1.y);
            fma2(vacc[4], pp, (u64)v2.x); fma2(vacc[5], pp, (u64)v2.y);
            fma2(vacc[6], pp, (u64)v3.x); fma2(vacc[7], pp, (u64)v3.y);
        }
    }

    // -------- write partials --------
    sSum[ia * 4 + jq] = runSum;
    __syncthreads();
    if (tid < 64) {
        float s = sSum[tid * 4] + sSum[tid * 4 + 1] + sSum[tid * 4 + 2] + sSum[tid * 4 + 3];
        g_psum[jc][tok0 + tid] = s;
    }
    float* dst = &g_pacc[jc][(tok0 + ia) * 64 + jq * 16];
    #pragma unroll
    for (int e = 0; e < 4; e++) {
        float2 f0 = up2(vacc[2 * e]);
        float2 f1 = up2(vacc[2 * e + 1]);
        float4 o = make_float4(f0.x, f0.y, f1.x, f1.y);
        *(float4*)&dst[e * 4] = o;
    }
}

// ---------------- merge partials -> g_ao -------------------------------------
__global__ void merge_kernel()
{
    int idx = blockIdx.x * 256 + threadIdx.x;    // 262144 items
    int tok = idx >> 4, c4 = idx & 15;
    int i = tok & 511;
    float4 a = *(const float4*)&g_pacc[0][tok * 64 + c4 * 4];
    float s = g_psum[0][tok];
    if (i >= 64) {
        float4 b = *(const float4*)&g_pacc[1][tok * 64 + c4 * 4];
        a.x += b.x; a.y += b.y; a.z += b.z; a.w += b.w;
        s += g_psum[1][tok];
    }
    float inv = 1.f / s;
    int bh = tok >> 9;
    int b = bh >> 4, h = bh & 15;
    float4 o = make_float4(a.x * inv, a.y * inv, a.z * inv, a.w * inv);
    *(float4*)&g_ao[(b * 512 + i) * 1024 + h * 64 + c4 * 4] = o;
}

// ---------------- launch ------------------------------------------------------
extern "C" void kernel_launch(void* const* d_in, const int* in_sizes, int n_in,
                              void* d_out, int out_size)
{
    const float* x    = (const float*)d_in[0];
    const float* Wq   = (const float*)d_in[1];
    const float* Wk   = (const float*)d_in[2];
    const float* Wv   = (const float*)d_in[3];
    const float* Wo   = (const float*)d_in[4];
    const float* Wqm  = (const float*)d_in[5];
    const float* Wkm  = (const float*)d_in[6];
    const float* Wmet = (const float*)d_in[7];
    const float* temp = (const float*)d_in[8];
    float*       out  = (float*)d_out;

    gemm2<<<dim3(16, 8, 3), 256>>>(x, Wq, Wk, Wv, nullptr, 0);
    metric_kernel<<<BHT / 8, 256>>>(Wqm, Wkm, Wmet);
    attn2<<<dim3(15, 32), 256>>>(temp);
    merge_kernel<<<1024, 256>>>();
    gemm2<<<dim3(16, 8, 1), 256>>>(nullptr, Wo, nullptr, nullptr, out, 1);
}

// round 3
// speedup vs baseline: 1.2225x; 1.2225x over previous
#include <cuda_runtime.h>
#include <math.h>

#define Bb   2
#define Tt   512
#define Hh   16
#define BHT  16384

#define TQ 128
#define TJ 64
#define USTRIDE 132

// ---------------- scratch ----------------------------------------------------
__device__ float g_q [BHT*64];
__device__ float g_k [BHT*64];
__device__ float g_v [BHT*64];
__device__ float g_qm[BHT*32];
__device__ float g_km[BHT*32];
__device__ float g_q2[BHT];
__device__ float g_k2[BHT];
__device__ float g_U [BHT*128];
__device__ float g_Uq[BHT*4];
__device__ float g_ao[Bb*Tt*1024];

// ---------------- tf32 helpers ------------------------------------------------
__device__ __forceinline__ uint2 spl(float x) {
    unsigned h, l;
    asm("cvt.rna.tf32.f32 %0,%1;" : "=r"(h) : "f"(x));
    float hf = __uint_as_float(h);
    asm("cvt.rna.tf32.f32 %0,%1;" : "=r"(l) : "f"(x - hf));
    return make_uint2(h, l);
}

__device__ __forceinline__ void mma8(float* c,
    unsigned a0, unsigned a1, unsigned a2, unsigned a3,
    unsigned b0, unsigned b1)
{
    asm volatile(
        "mma.sync.aligned.m16n8k8.row.col.f32.tf32.tf32.f32 "
        "{%0,%1,%2,%3},{%4,%5,%6,%7},{%8,%9},{%0,%1,%2,%3};"
        : "+f"(c[0]), "+f"(c[1]), "+f"(c[2]), "+f"(c[3])
        : "r"(a0), "r"(a1), "r"(a2), "r"(a3), "r"(b0), "r"(b1));
}

// ---------------- GEMM via tensor cores (3xTF32) ------------------------------
// C[1024,1024] = A @ W.  CTA tile 128x64, BK=32, 8 warps of 32x32.
// mode 0: A = x, W by blockIdx.z (Wq/Wk/Wv), head-split store to g_q/g_k/g_v
// mode 1: A = g_ao, W = W0 (Wo), plain store to Cout
#define SA_STR 36
#define SB_STR 68
#define GEMM_SMEM ((128*SA_STR + 32*SB_STR) * 8)

__global__ void __launch_bounds__(256) gemm_tc(
    const float* __restrict__ A,
    const float* __restrict__ W0, const float* __restrict__ W1,
    const float* __restrict__ W2,
    float* __restrict__ Cout, int mode)
{
    extern __shared__ uint2 sm2[];
    uint2* sA = sm2;                 // [128][SA_STR]
    uint2* sB = sm2 + 128 * SA_STR;  // [32][SB_STR]

    const float* Ap = (mode == 0) ? A : g_ao;
    const float* Wm = (mode == 0)
        ? (blockIdx.z == 0 ? W0 : (blockIdx.z == 1 ? W1 : W2))
        : W0;

    int tid  = threadIdx.x;
    int lane = tid & 31;
    int wid  = tid >> 5;
    int wm   = wid & 3;          // 4 warps over M (4*32=128)
    int wn   = wid >> 2;         // 2 warps over N (2*32=64)
    int g    = lane >> 2;
    int tg   = lane & 3;
    int row0 = blockIdx.y * 128;
    int col0 = blockIdx.x * 64;

    // global-load assignments
    int aRow[4], aC4[4], sAi[4];
    #pragma unroll
    for (int e = 0; e < 4; e++) {
        int idx = tid + e * 256;          // 1024 float4 of A tile (128x32)
        aRow[e] = idx >> 3; aC4[e] = idx & 7;
        sAi[e]  = aRow[e] * SA_STR + aC4[e] * 4;
    }
    int bRow[2], bC4[2], sBi[2];
    #pragma unroll
    for (int e = 0; e < 2; e++) {
        int idx = tid + e * 256;          // 512 float4 of B tile (32x64)
        bRow[e] = idx >> 4; bC4[e] = idx & 15;
        sBi[e]  = bRow[e] * SB_STR + bC4[e] * 4;
    }

    float acc[2][4][4];
    #pragma unroll
    for (int mt = 0; mt < 2; mt++)
        #pragma unroll
        for (int nt = 0; nt < 4; nt++)
            #pragma unroll
            for (int e = 0; e < 4; e++) acc[mt][nt][e] = 0.f;

    // preload tile 0
    float4 av[4], bv[2];
    #pragma unroll
    for (int e = 0; e < 4; e++)
        av[e] = *(const float4*)&Ap[(row0 + aRow[e]) * 1024 + aC4[e] * 4];
    #pragma unroll
    for (int e = 0; e < 2; e++)
        bv[e] = *(const float4*)&Wm[bRow[e] * 1024 + col0 + bC4[e] * 4];

    for (int t = 0; t < 32; t++) {
        __syncthreads();
        #pragma unroll
        for (int e = 0; e < 4; e++) {
            uint2* d = &sA[sAi[e]];
            d[0] = spl(av[e].x); d[1] = spl(av[e].y);
            d[2] = spl(av[e].z); d[3] = spl(av[e].w);
        }
        #pragma unroll
        for (int e = 0; e < 2; e++) {
            uint2* d = &sB[sBi[e]];
            d[0] = spl(bv[e].x); d[1] = spl(bv[e].y);
            d[2] = spl(bv[e].z); d[3] = spl(bv[e].w);
        }
        __syncthreads();

        if (t < 31) {
            int k0 = (t + 1) * 32;
            #pragma unroll
            for (int e = 0; e < 4; e++)
                av[e] = *(const float4*)&Ap[(row0 + aRow[e]) * 1024 + k0 + aC4[e] * 4];
            #pragma unroll
            for (int e = 0; e < 2; e++)
                bv[e] = *(const float4*)&Wm[(k0 + bRow[e]) * 1024 + col0 + bC4[e] * 4];
        }

        #pragma unroll
        for (int kk = 0; kk < 32; kk += 8) {
            uint2 Afr[2][4];
            #pragma unroll
            for (int mt = 0; mt < 2; mt++) {
                int rb = (wm * 32 + mt * 16 + g) * SA_STR + kk + tg;
                Afr[mt][0] = sA[rb];
                Afr[mt][2] = sA[rb + 4];
                Afr[mt][1] = sA[rb + 8 * SA_STR];
                Afr[mt][3] = sA[rb + 8 * SA_STR + 4];
            }
            #pragma unroll
            for (int nt = 0; nt < 4; nt++) {
                int cb = (kk + tg) * SB_STR + wn * 32 + nt * 8 + g;
                uint2 B0 = sB[cb];
                uint2 B1 = sB[cb + 4 * SB_STR];
                #pragma unroll
                for (int mt = 0; mt < 2; mt++) {
                    float* c = acc[mt][nt];
                    mma8(c, Afr[mt][0].x, Afr[mt][1].x, Afr[mt][2].x, Afr[mt][3].x,
                         B0.x, B1.x);                               // hi*hi
                    mma8(c, Afr[mt][0].x, Afr[mt][1].x, Afr[mt][2].x, Afr[mt][3].x,
                         B0.y, B1.y);                               // hi*lo
                    mma8(c, Afr[mt][0].y, Afr[mt][1].y, Afr[mt][2].y, Afr[mt][3].y,
                         B0.x, B1.x);                               // lo*hi
                }
            }
        }
    }

    // epilogue: c0,c1 -> (row, col..col+1); c2,c3 -> (row+8, ...)
    if (mode == 1) {
        #pragma unroll
        for (int mt = 0; mt < 2; mt++) {
            int row = row0 + wm * 32 + mt * 16 + g;
            #pragma unroll
            for (int nt = 0; nt < 4; nt++) {
                int col = col0 + wn * 32 + nt * 8 + 2 * tg;
                *(float2*)&Cout[row * 1024 + col] =
                    make_float2(acc[mt][nt][0], acc[mt][nt][1]);
                *(float2*)&Cout[(row + 8) * 1024 + col] =
                    make_float2(acc[mt][nt][2], acc[mt][nt][3]);
            }
        }
    } else {
        int z = blockIdx.z;
        float* dst = (z == 0) ? g_q : (z == 1) ? g_k : g_v;
        int h = blockIdx.x;               // col tile == head (64-wide)
        #pragma unroll
        for (int mt = 0; mt < 2; mt++) {
            int row = row0 + wm * 32 + mt * 16 + g;
            int b0r = row >> 9, t0r = row & 511;
            int b1r = (row + 8) >> 9, t1r = (row + 8) & 511;
            #pragma unroll
            for (int nt = 0; nt < 4; nt++) {
                int col = wn * 32 + nt * 8 + 2 * tg;   // within-head 0..63
                *(float2*)&dst[(((b0r << 4) + h) * 512 + t0r) * 64 + col] =
                    make_float2(acc[mt][nt][0], acc[mt][nt][1]);
                *(float2*)&dst[(((b1r << 4) + h) * 512 + t1r) * 64 + col] =
                    make_float2(acc[mt][nt][2], acc[mt][nt][3]);
            }
        }
    }
}

// ---------------- RoPE (in place on g_q, g_k) -------------------------------
__global__ void rope_kernel()
{
    int idx = blockIdx.x * blockDim.x + threadIdx.x;
    if (idx >= BHT * 32) return;
    int tok = idx >> 5;
    int j   = idx & 31;
    int t   = tok & 511;
    float inv = expf(-((float)(2 * j) / 64.0f) * 9.210340371976184f);
    float fr  = (float)t * inv;
    float s, c;
    sincosf(fr, &s, &c);

    float* q = g_q + tok * 64;
    float x1 = q[j], x2 = q[j + 32];
    q[j]      = x1 * c - x2 * s;
    q[j + 32] = x1 * s + x2 * c;

    float* k = g_k + tok * 64;
    x1 = k[j]; x2 = k[j + 32];
    k[j]      = x1 * c - x2 * s;
    k[j + 32] = x1 * s + x2 * c;
}

// ---------------- metric: qm, km, q2, k2, U, Uq -----------------------------
__global__ void __launch_bounds__(256) metric_kernel(
    const float* __restrict__ Wqm, const float* __restrict__ Wkm,
    const float* __restrict__ Wmetric)
{
    __shared__ float sWqm[64 * 32];
    __shared__ float sWkm[64 * 32];
    __shared__ float sWm [32 * 128];
    int tid = threadIdx.x;
    for (int i = tid; i < 64 * 32; i += 256) { sWqm[i] = Wqm[i]; sWkm[i] = Wkm[i]; }
    for (int i = tid; i < 32 * 128; i += 256) { sWm[i] = Wmetric[i]; }
    __syncthreads();

    const unsigned FULL = 0xffffffffu;
    int w = tid >> 5, lane = tid & 31;
    int tok = blockIdx.x * 8 + w;

    const float* q = g_q + tok * 64;
    const float* k = g_k + tok * 64;
    float a0 = q[lane], a1 = q[lane + 32];
    float b0 = k[lane], b1 = k[lane + 32];

    float accq = 0.f, acck = 0.f;
    #pragma unroll
    for (int d = 0; d < 32; d++) {
        float qd = __shfl_sync(FULL, a0, d);
        float kd = __shfl_sync(FULL, b0, d);
        accq += qd * sWqm[d * 32 + lane];
        acck += kd * sWkm[d * 32 + lane];
    }
    #pragma unroll
    for (int d = 0; d < 32; d++) {
        float qd = __shfl_sync(FULL, a1, d);
        float kd = __shfl_sync(FULL, b1, d);
        accq += qd * sWqm[(d + 32) * 32 + lane];
        acck += kd * sWkm[(d + 32) * 32 + lane];
    }
    float qmv = 1.f / (1.f + expf(-accq));
    float kmv = 1.f / (1.f + expf(-acck));
    g_qm[tok * 32 + lane] = qmv;
    g_km[tok * 32 + lane] = kmv;

    float q2 = qmv * qmv, k2 = kmv * kmv;
    #pragma unroll
    for (int o = 16; o > 0; o >>= 1) {
        q2 += __shfl_xor_sync(FULL, q2, o);
        k2 += __shfl_xor_sync(FULL, k2, o);
    }
    if (lane == 0) { g_q2[tok] = q2; g_k2[tok] = k2; }

    float u0 = 0.f, u1 = 0.f, u2 = 0.f, u3 = 0.f;
    #pragma unroll
    for (int d = 0; d < 32; d++) {
        float qd = __shfl_sync(FULL, qmv, d);
        float4 wv = *(const float4*)&sWm[d * 128 + lane * 4];
        u0 += qd * wv.x; u1 += qd * wv.y; u2 += qd * wv.z; u3 += qd * wv.w;
    }
    *(float4*)&g_U[tok * 128 + lane * 4] = make_float4(u0, u1, u2, u3);

    float p0 = u0 * qmv, p1 = u1 * qmv, p2 = u2 * qmv, p3 = u3 * qmv;
    #pragma unroll
    for (int o = 16; o > 0; o >>= 1) {
        p0 += __shfl_xor_sync(FULL, p0, o);
        p1 += __shfl_xor_sync(FULL, p1, o);
        p2 += __shfl_xor_sync(FULL, p2, o);
        p3 += __shfl_xor_sync(FULL, p3, o);
    }
    if (lane == 0) {
        g_Uq[tok * 4 + 0] = p0; g_Uq[tok * 4 + 1] = p1;
        g_Uq[tok * 4 + 2] = p2; g_Uq[tok * 4 + 3] = p3;
    }
}

// ---------------- attention (R1, known-good 181us) ----------------------------
__global__ void __launch_bounds__(256, 1) attn_kernel(const float* __restrict__ temp_ptr)
{
    extern __shared__ float sm[];
    float* sU  = sm;                        // TQ*USTRIDE
    float* sKm = sU + TQ * USTRIDE;         // 2 * TJ*32
    float* sV  = sKm + 2 * TJ * 32;         // 2 * TJ*64
    float* sK2 = sV + 2 * TJ * 64;          // 2 * TJ

    int bh = blockIdx.y;
    int b = bh >> 4, h = bh & 15;
    int qt = blockIdx.x;
    int tid = threadIdx.x;
    int qi = tid & 127;
    int half = tid >> 7;
    int i = qt * TQ + qi;
    int tokBase = bh * Tt;
    int tok = tokBase + i;

    float qm[32];
    #pragma unroll
    for (int d = 0; d < 32; d++) qm[d] = g_qm[tok * 32 + d];
    float Uq0 = g_Uq[tok * 4 + 0], Uq1 = g_Uq[tok * 4 + 1];
    float Uq2 = g_Uq[tok * 4 + 2], Uq3 = g_Uq[tok * 4 + 3];
    float q2  = g_q2[tok];
    float invT = 1.0f / fmaxf(temp_ptr[0], 0.5f);

    for (int idx = tid; idx < TQ * 32; idx += 256) {
        int r = idx >> 5, c4 = idx & 31;
        float4 v = *(const float4*)&g_U[(tokBase + qt * TQ + r) * 128 + c4 * 4];
        *(float4*)&sU[r * USTRIDE + c4 * 4] = v;
    }

    float acc[64];
    #pragma unroll
    for (int c = 0; c < 64; c++) acc[c] = 0.f;
    float lsum = 0.f;

    float* myKm = sKm + half * TJ * 32;
    float* myV  = sV  + half * TJ * 64;
    float* myK2 = sK2 + half * TJ;
    int lt = tid & 127;

    int nS = qt + 1;
    for (int s = 0; s < nS; s++) {
        int jt = 2 * s + half;
        int j0 = jt * TJ;
        __syncthreads();
        {
            int tokJ = tokBase + j0;
            #pragma unroll
            for (int p = 0; p < 4; p++) {
                int e = lt + p * 128;
                *(float4*)&myKm[e * 4] = *(const float4*)&g_km[tokJ * 32 + e * 4];
            }
            #pragma unroll
            for (int p = 0; p < 8; p++) {
                int e = lt + p * 128;
                *(float4*)&myV[e * 4] = *(const float4*)&g_v[tokJ * 64 + e * 4];
            }
            if (lt < TJ) myK2[lt] = g_k2[tokJ + lt];
        }
        __syncthreads();

        if (j0 <= i) {
            int jend = min(TJ, i - j0 + 1);
            for (int jj = 0; jj < jend; jj++) {
                const float4* km4 = (const float4*)&myKm[jj * 32];
                float qk = 0.f, u0b = 0.f, u1b = 0.f, u2b = 0.f, u3b = 0.f;
                #pragma unroll
                for (int dd = 0; dd < 8; dd++) {
                    float4 kv = km4[dd];
                    qk += qm[dd*4+0]*kv.x + qm[dd*4+1]*kv.y
                        + qm[dd*4+2]*kv.z + qm[dd*4+3]*kv.w;
                    float4 Ua = *(const float4*)&sU[qi*USTRIDE + (dd*4+0)*4];
                    float4 Ub = *(const float4*)&sU[qi*USTRIDE + (dd*4+1)*4];
                    float4 Uc = *(const float4*)&sU[qi*USTRIDE + (dd*4+2)*4];
                    float4 Ud = *(const float4*)&sU[qi*USTRIDE + (dd*4+3)*4];
                    u0b += kv.x*Ua.x + kv.y*Ub.x + kv.z*Uc.x + kv.w*Ud.x;
                    u1b += kv.x*Ua.y + kv.y*Ub.y + kv.z*Uc.y + kv.w*Ud.y;
                    u2b += kv.x*Ua.z + kv.y*Ub.z + kv.z*Uc.z + kv.w*Ud.z;
                    u3b += kv.x*Ua.w + kv.y*Ub.w + kv.z*Uc.w + kv.w*Ud.w;
                }
                float e0 = Uq0-u0b, e1 = Uq1-u1b, e2 = Uq2-u2b, e3 = Uq3-u3b;
                float dist = q2 + myK2[jj] - 2.f*qk + e0*e0 + e1*e1 + e2*e2 + e3*e3;
                dist = fmaxf(dist, 0.f);
                float p = expf(-dist * invT);
                lsum += p;
                const float4* v4 = (const float4*)&myV[jj * 64];
                #pragma unroll
                for (int c = 0; c < 16; c++) {
                    float4 vv = v4[c];
                    acc[c*4+0] += p*vv.x; acc[c*4+1] += p*vv.y;
                    acc[c*4+2] += p*vv.z; acc[c*4+3] += p*vv.w;
                }
            }
        }
    }

    __syncthreads();
    if (half == 1) {
        float* mb = sU + qi * 66;
        #pragma unroll
        for (int c = 0; c < 64; c++) mb[c] = acc[c];
        mb[64] = lsum;
    }
    __syncthreads();
    if (half == 0) {
        const float* mb = sU + qi * 66;
        lsum += mb[64];
        float inv = 1.f / lsum;
        float* outp = g_ao + ((size_t)(b * Tt + i)) * 1024 + h * 64;
        #pragma unroll
        for (int c = 0; c < 64; c += 4) {
            float4 o;
            o.x = (acc[c+0] + mb[c+0]) * inv;
            o.y = (acc[c+1] + mb[c+1]) * inv;
            o.z = (acc[c+2] + mb[c+2]) * inv;
            o.w = (acc[c+3] + mb[c+3]) * inv;
            *(float4*)&outp[c] = o;
        }
    }
}

// ---------------- launch ------------------------------------------------------
extern "C" void kernel_launch(void* const* d_in, const int* in_sizes, int n_in,
                              void* d_out, int out_size)
{
    const float* x    = (const float*)d_in[0];
    const float* Wq   = (const float*)d_in[1];
    const float* Wk   = (const float*)d_in[2];
    const float* Wv   = (const float*)d_in[3];
    const float* Wo   = (const float*)d_in[4];
    const float* Wqm  = (const float*)d_in[5];
    const float* Wkm  = (const float*)d_in[6];
    const float* Wmet = (const float*)d_in[7];
    const float* temp = (const float*)d_in[8];
    float*       out  = (float*)d_out;

    const int attn_smem = (TQ*USTRIDE + 2*TJ*32 + 2*TJ*64 + 2*TJ) * 4;
    cudaFuncSetAttribute(attn_kernel,
                         cudaFuncAttributeMaxDynamicSharedMemorySize, attn_smem);
    cudaFuncSetAttribute(gemm_tc,
                         cudaFuncAttributeMaxDynamicSharedMemorySize, GEMM_SMEM);

    gemm_tc<<<dim3(16, 8, 3), 256, GEMM_SMEM>>>(x, Wq, Wk, Wv, nullptr, 0);
    rope_kernel<<<(BHT * 32) / 256, 256>>>();
    metric_kernel<<<BHT / 8, 256>>>(Wqm, Wkm, Wmet);
    attn_kernel<<<dim3(Tt / TQ, Bb * Hh), 256, attn_smem>>>(temp);
    gemm_tc<<<dim3(16, 8, 1), 256, GEMM_SMEM>>>(nullptr, Wo, nullptr, nullptr, out, 1);
}